// round 7
// baseline (speedup 1.0000x reference)
#include <cuda_runtime.h>
#include <cuda_bf16.h>
#include <cstdint>
#include <cstddef>

// ---------------------------------------------------------------------------
// Problem constants
// ---------------------------------------------------------------------------
#define DIMC   384
#define HEADS  12
#define HD     32
#define NTOK   49
#define BWIN   4096
#define NWIN   256
#define MROWS  (BWIN * NTOK)     // 200704
#define QKVN   (3 * DIMC)        // 1152
#define QSCALE 0.17677669529663687f  // 1/sqrt(32)

// ---------------------------------------------------------------------------
// Scratch (__device__ globals; no runtime allocation)
// ---------------------------------------------------------------------------
__device__ float g_qkv[(size_t)MROWS * QKVN];           // qkv activations fp32
__device__ __nv_bfloat16 g_xhi[(size_t)MROWS * DIMC];   // x split
__device__ __nv_bfloat16 g_xlo[(size_t)MROWS * DIMC];
__device__ __nv_bfloat16 g_ahi[(size_t)MROWS * DIMC];   // attn out split
__device__ __nv_bfloat16 g_alo[(size_t)MROWS * DIMC];
__device__ __nv_bfloat16 g_wt_hi[(size_t)(QKVN + DIMC) * DIMC];  // W^T split
__device__ __nv_bfloat16 g_wt_lo[(size_t)(QKVN + DIMC) * DIMC];
__device__ float g_bias[HEADS * NTOK * NTOK];           // pre-clipped rel bias

// ---------------------------------------------------------------------------
// Helpers (non-'a' ISA: ldmatrix / mma.sync / cp.async)
// ---------------------------------------------------------------------------
__device__ __forceinline__ uint32_t smem_u32(const void* p) {
    uint32_t a;
    asm("{ .reg .u64 t; cvta.to.shared.u64 t, %1; cvt.u32.u64 %0, t; }"
        : "=r"(a) : "l"(p));
    return a;
}
__device__ __forceinline__ uint32_t sw128(uint32_t off) {
    return off ^ ((off >> 3) & 0x70);
}
__device__ __forceinline__ void ldsm4(uint32_t (&r)[4], uint32_t addr) {
    asm volatile("ldmatrix.sync.aligned.m8n8.x4.shared.b16 {%0,%1,%2,%3}, [%4];"
        : "=r"(r[0]), "=r"(r[1]), "=r"(r[2]), "=r"(r[3]) : "r"(addr));
}
__device__ __forceinline__ void mma16816(float (&d)[4], const uint32_t (&a)[4],
                                         uint32_t b0, uint32_t b1) {
    asm volatile(
        "mma.sync.aligned.m16n8k16.row.col.f32.bf16.bf16.f32 "
        "{%0,%1,%2,%3}, {%4,%5,%6,%7}, {%8,%9}, {%0,%1,%2,%3};"
        : "+f"(d[0]), "+f"(d[1]), "+f"(d[2]), "+f"(d[3])
        : "r"(a[0]), "r"(a[1]), "r"(a[2]), "r"(a[3]), "r"(b0), "r"(b1));
}
__device__ __forceinline__ void cp16(uint32_t dst, const void* src) {
    asm volatile("cp.async.cg.shared.global [%0], [%1], 16;"
                 :: "r"(dst), "l"(src));
}
#define CP_COMMIT() asm volatile("cp.async.commit_group;" ::: "memory")
#define CP_WAIT1()  asm volatile("cp.async.wait_group 1;" ::: "memory")

// ---------------------------------------------------------------------------
// Prep kernels
// ---------------------------------------------------------------------------
__global__ void prep_w_kernel(const float* __restrict__ W,
                              __nv_bfloat16* __restrict__ hi,
                              __nv_bfloat16* __restrict__ lo,
                              int K, int N) {
    int idx = blockIdx.x * blockDim.x + threadIdx.x;
    if (idx >= N * K) return;
    int n = idx / K, k = idx % K;
    float x = W[(size_t)k * N + n];
    __nv_bfloat16 h = __float2bfloat16(x);
    hi[idx] = h;
    lo[idx] = __float2bfloat16(x - __bfloat162float(h));
}

__global__ void prep_x_kernel(const float* __restrict__ x,
                              __nv_bfloat16* __restrict__ hi,
                              __nv_bfloat16* __restrict__ lo, size_t n4) {
    size_t i = (size_t)blockIdx.x * blockDim.x + threadIdx.x;
    if (i >= n4) return;
    float4 xv = ((const float4*)x)[i];
    __nv_bfloat162 h0 = __floats2bfloat162_rn(xv.x, xv.y);
    __nv_bfloat162 h1 = __floats2bfloat162_rn(xv.z, xv.w);
    __nv_bfloat162 l0 = __floats2bfloat162_rn(xv.x - __low2float(h0),
                                              xv.y - __high2float(h0));
    __nv_bfloat162 l1 = __floats2bfloat162_rn(xv.z - __low2float(h1),
                                              xv.w - __high2float(h1));
    ((uint2*)hi)[i] = make_uint2(*(uint32_t*)&h0, *(uint32_t*)&h1);
    ((uint2*)lo)[i] = make_uint2(*(uint32_t*)&l0, *(uint32_t*)&l1);
}

__global__ void prep_bias_kernel(const float* __restrict__ table,
                                 const int* __restrict__ idx,
                                 float* __restrict__ out) {
    int e = blockIdx.x * blockDim.x + threadIdx.x;
    if (e >= HEADS * NTOK * NTOK) return;
    int h = e / (NTOK * NTOK), nm = e % (NTOK * NTOK);
    float b = table[idx[nm] * HEADS + h];
    out[e] = fminf(fmaxf(b, -5.f), 5.f);
}

// ---------------------------------------------------------------------------
// HMMA bf16-split GEMM: C = A @ Wt^T + bias  (A, Wt pre-split bf16 hi/lo)
// Tile 128x128, BK=32, 3-stage cp.async pipeline, 256 threads (8 warps 4mx2n).
// Stage = 32KB: A tile 16KB + B tile 16KB; row = 128B [hi 64B | lo 64B], SW128.
// 96KB total smem -> 2 CTAs/SM (16 warps) for latency hiding.
// ---------------------------------------------------------------------------
#define GEMM_SMEM_BYTES (3 * 32768)

template <bool QKV>
__global__ __launch_bounds__(256, 2) void mma_gemm(
    const __nv_bfloat16* __restrict__ Ahi, const __nv_bfloat16* __restrict__ Alo,
    const __nv_bfloat16* __restrict__ Bhi, const __nv_bfloat16* __restrict__ Blo,
    const float* __restrict__ bias,
    float* __restrict__ C, int M, int N, int K)
{
    extern __shared__ char smem[];
    const uint32_t sb = smem_u32(smem);
    const int tid  = threadIdx.x;
    const int lane = tid & 31;
    const int wid  = tid >> 5;
    const int wm   = wid & 3;
    const int wn   = wid >> 2;
    const int bm = blockIdx.y * 128;
    const int bn = blockIdx.x * 128;
    const int NCH = K / 32;            // 12

    // staging map: thread -> row (0..127) and 16-elem chunk pair p (0/1)
    const int crow = tid >> 1;
    const int cp   = tid & 1;

    auto cp_stage = [&](int s, int ch) {
        const int k0 = ch * 32;
        const uint32_t st = sb + s * 32768;
        const uint32_t h0 = sw128((uint32_t)(crow * 128 + cp * 32));
        const uint32_t h1 = sw128((uint32_t)(crow * 128 + cp * 32 + 16));
        const uint32_t l0 = sw128((uint32_t)(crow * 128 + 64 + cp * 32));
        const uint32_t l1 = sw128((uint32_t)(crow * 128 + 64 + cp * 32 + 16));
        const size_t ga = (size_t)(bm + crow) * K + k0 + cp * 16;
        const size_t gb = (size_t)(bn + crow) * K + k0 + cp * 16;
        cp16(st + h0,         Ahi + ga);
        cp16(st + h1,         Ahi + ga + 8);
        cp16(st + l0,         Alo + ga);
        cp16(st + l1,         Alo + ga + 8);
        cp16(st + 16384 + h0, Bhi + gb);
        cp16(st + 16384 + h1, Bhi + gb + 8);
        cp16(st + 16384 + l0, Blo + gb);
        cp16(st + 16384 + l1, Blo + gb + 8);
    };

    float acc[2][8][4] = {};

    auto domma = [&](int s) {
        const uint32_t sA = sb + s * 32768;
        const uint32_t sB = sA + 16384;
        #pragma unroll
        for (int ks = 0; ks < 2; ks++) {
            const int chi = (2 * ks + (lane >> 4)) * 16;   // hi chunk byte
            const int clo = chi + 64;                      // lo chunk byte
            uint32_t ah[2][4], al[2][4];
            #pragma unroll
            for (int mt = 0; mt < 2; mt++) {
                const int r = wm * 32 + mt * 16 + (lane & 15);
                ldsm4(ah[mt], sA + sw128((uint32_t)(r * 128 + chi)));
                ldsm4(al[mt], sA + sw128((uint32_t)(r * 128 + clo)));
            }
            uint32_t bh[4][4], bl[4][4];
            #pragma unroll
            for (int g = 0; g < 4; g++) {
                const int r = wn * 64 + g * 16 + (lane & 15);
                ldsm4(bh[g], sB + sw128((uint32_t)(r * 128 + chi)));
                ldsm4(bl[g], sB + sw128((uint32_t)(r * 128 + clo)));
            }
            #pragma unroll
            for (int mt = 0; mt < 2; mt++)
                #pragma unroll
                for (int nt = 0; nt < 8; nt++) {
                    const int g = nt >> 1, o = nt & 1;
                    mma16816(acc[mt][nt], ah[mt], bh[g][o], bh[g][o + 2]);
                    mma16816(acc[mt][nt], al[mt], bh[g][o], bh[g][o + 2]);
                    mma16816(acc[mt][nt], ah[mt], bl[g][o], bl[g][o + 2]);
                }
        }
    };

    // prologue: stages 0,1
    cp_stage(0, 0); CP_COMMIT();
    cp_stage(1, 1); CP_COMMIT();

    for (int ch = 0; ch < NCH; ch++) {
        const int s = ch % 3;
        CP_WAIT1();             // stage ch resident
        __syncthreads();
        if (ch + 2 < NCH) cp_stage((ch + 2) % 3, ch + 2);
        CP_COMMIT();            // commit every iter keeps group count uniform
        domma(s);
    }

    // epilogue: bias (+ q scaling), fp32 store
    const float qs = (QKV && bn < DIMC) ? QSCALE : 1.0f;
    #pragma unroll
    for (int mt = 0; mt < 2; mt++) {
        const int r0 = bm + wm * 32 + mt * 16 + (lane >> 2);
        #pragma unroll
        for (int nt = 0; nt < 8; nt++) {
            const int c0 = bn + wn * 64 + nt * 8 + (lane & 3) * 2;
            const float2 bv = *(const float2*)(bias + c0);
            float2 w0, w1;
            w0.x = (acc[mt][nt][0] + bv.x) * qs;
            w0.y = (acc[mt][nt][1] + bv.y) * qs;
            w1.x = (acc[mt][nt][2] + bv.x) * qs;
            w1.y = (acc[mt][nt][3] + bv.y) * qs;
            *(float2*)(C + (size_t)r0 * N + c0)       = w0;
            *(float2*)(C + (size_t)(r0 + 8) * N + c0) = w1;
        }
    }
}

// ---------------------------------------------------------------------------
// Attention v2: register-tiled, CTA per (window b, head h), 128 threads.
// ---------------------------------------------------------------------------
__global__ __launch_bounds__(128) void attn_kernel(
    const float* __restrict__ qkv, const float* __restrict__ mask,
    const float* __restrict__ biasArr,
    __nv_bfloat16* __restrict__ ohi, __nv_bfloat16* __restrict__ olo)
{
    const int b = blockIdx.x / HEADS;
    const int h = blockIdx.x % HEADS;
    const int tid = threadIdx.x;

    __shared__ float q[NTOK * HD];
    __shared__ float k[NTOK * HD];
    __shared__ float v[NTOK * HD];
    __shared__ float S[NTOK * NTOK];

    const float* base = qkv + (size_t)b * NTOK * QKVN + h * HD;
    for (int e = tid; e < NTOK * 8; e += 128) {
        const int n = e >> 3, j = e & 7;
        const float* row = base + (size_t)n * QKVN + j * 4;
        ((float4*)q)[e] = *(const float4*)(row);
        ((float4*)k)[e] = *(const float4*)(row + DIMC);
        ((float4*)v)[e] = *(const float4*)(row + 2 * DIMC);
    }
    __syncthreads();

    const float* mrow = mask + (size_t)(b % NWIN) * NTOK * NTOK;
    const float* brow = biasArr + h * NTOK * NTOK;

    // phase 1: S = clip(q.k + mask + bias)
    if (tid < 98) {
        const int n = tid >> 1, half = tid & 1;
        float qr[32];
        #pragma unroll
        for (int j = 0; j < 8; j++)
            *(float4*)(qr + 4 * j) = ((float4*)q)[n * 8 + j];
        const int m0 = half * 25;
        const int mc = half ? 24 : 25;
        for (int i = 0; i < mc; i++) {
            const int m = m0 + i;
            float s = 0.f;
            #pragma unroll
            for (int j = 0; j < 8; j++) {
                float4 kv = ((float4*)k)[m * 8 + j];
                s += qr[4*j]   * kv.x + qr[4*j+1] * kv.y
                   + qr[4*j+2] * kv.z + qr[4*j+3] * kv.w;
            }
            const int nm = n * NTOK + m;
            s = s + mrow[nm] + brow[nm];
            S[nm] = fminf(fmaxf(s, -10.f), 10.f);
        }
    }
    __syncthreads();

    // phase 2: row softmax
    if (tid < NTOK) {
        float* r = S + tid * NTOK;
        float mx = -1e30f;
        #pragma unroll
        for (int m = 0; m < NTOK; m++) mx = fmaxf(mx, r[m]);
        float sum = 0.f;
        #pragma unroll
        for (int m = 0; m < NTOK; m++) {
            float e = __expf(r[m] - mx);
            r[m] = e;
            sum += e;
        }
        const float inv = 1.f / sum;
        #pragma unroll
        for (int m = 0; m < NTOK; m++) r[m] *= inv;
    }
    __syncthreads();

    // phase 3: out = S@v, emit bf16 hi/lo
    if (tid < 98) {
        const int n = tid >> 1, dh = (tid & 1) * 16;
        float acc[16] = {};
        for (int m = 0; m < NTOK; m++) {
            const float p = S[n * NTOK + m];
            #pragma unroll
            for (int j = 0; j < 4; j++) {
                float4 vv = *(const float4*)(v + m * HD + dh + 4 * j);
                acc[4*j]   += p * vv.x;
                acc[4*j+1] += p * vv.y;
                acc[4*j+2] += p * vv.z;
                acc[4*j+3] += p * vv.w;
            }
        }
        const size_t o = (size_t)(b * NTOK + n) * DIMC + h * HD + dh;
        uint32_t hw[8], lw[8];
        #pragma unroll
        for (int p = 0; p < 8; p++) {
            __nv_bfloat162 hp = __floats2bfloat162_rn(acc[2*p], acc[2*p+1]);
            __nv_bfloat162 lp = __floats2bfloat162_rn(
                acc[2*p]   - __low2float(hp),
                acc[2*p+1] - __high2float(hp));
            hw[p] = *(uint32_t*)&hp;
            lw[p] = *(uint32_t*)&lp;
        }
        *(uint4*)(ohi + o)     = make_uint4(hw[0], hw[1], hw[2], hw[3]);
        *(uint4*)(ohi + o + 8) = make_uint4(hw[4], hw[5], hw[6], hw[7]);
        *(uint4*)(olo + o)     = make_uint4(lw[0], lw[1], lw[2], lw[3]);
        *(uint4*)(olo + o + 8) = make_uint4(lw[4], lw[5], lw[6], lw[7]);
    }
}

// ---------------------------------------------------------------------------
extern "C" void kernel_launch(void* const* d_in, const int* in_sizes, int n_in,
                              void* d_out, int out_size)
{
    const float* x         = (const float*)d_in[0];
    const float* mask      = (const float*)d_in[1];
    const float* qkv_w     = (const float*)d_in[2];
    const float* qkv_b     = (const float*)d_in[3];
    const float* proj_w    = (const float*)d_in[4];
    const float* proj_b    = (const float*)d_in[5];
    const float* rel_table = (const float*)d_in[6];
    const int*   rel_index = (const int*)d_in[7];
    float*       out       = (float*)d_out;

    float *qkvbuf = nullptr, *biasbuf = nullptr;
    __nv_bfloat16 *xhi, *xlo, *ahi, *alo, *wt_hi, *wt_lo;
    cudaGetSymbolAddress((void**)&qkvbuf, g_qkv);
    cudaGetSymbolAddress((void**)&biasbuf, g_bias);
    cudaGetSymbolAddress((void**)&xhi, g_xhi);
    cudaGetSymbolAddress((void**)&xlo, g_xlo);
    cudaGetSymbolAddress((void**)&ahi, g_ahi);
    cudaGetSymbolAddress((void**)&alo, g_alo);
    cudaGetSymbolAddress((void**)&wt_hi, g_wt_hi);
    cudaGetSymbolAddress((void**)&wt_lo, g_wt_lo);

    static int _once = []() {
        cudaFuncSetAttribute(mma_gemm<true>,
            cudaFuncAttributeMaxDynamicSharedMemorySize, GEMM_SMEM_BYTES);
        cudaFuncSetAttribute(mma_gemm<false>,
            cudaFuncAttributeMaxDynamicSharedMemorySize, GEMM_SMEM_BYTES);
        return 0;
    }();
    (void)_once;

    const size_t proj_off = (size_t)QKVN * DIMC;

    // 0) preps
    prep_w_kernel<<<(QKVN * DIMC + 255) / 256, 256>>>(
        qkv_w, wt_hi, wt_lo, DIMC, QKVN);
    prep_w_kernel<<<(DIMC * DIMC + 255) / 256, 256>>>(
        proj_w, wt_hi + proj_off, wt_lo + proj_off, DIMC, DIMC);
    prep_bias_kernel<<<(HEADS * NTOK * NTOK + 255) / 256, 256>>>(
        rel_table, rel_index, biasbuf);
    {
        const size_t n4 = (size_t)MROWS * DIMC / 4;
        prep_x_kernel<<<(unsigned)((n4 + 255) / 256), 256>>>(x, xhi, xlo, n4);
    }

    // 1) QKV GEMM (HMMA, 3-stage BK=32): [200704,384] @ [384,1152]
    {
        dim3 grid(QKVN / 128, MROWS / 128);  // (9, 1568)
        mma_gemm<true><<<grid, 256, GEMM_SMEM_BYTES>>>(
            xhi, xlo, wt_hi, wt_lo, qkv_b, qkvbuf, MROWS, QKVN, DIMC);
    }

    // 2) Attention per (window, head) -> bf16 hi/lo
    attn_kernel<<<BWIN * HEADS, 128>>>(qkvbuf, mask, biasbuf, ahi, alo);

    // 3) Proj GEMM: [200704,384] @ [384,384] -> out
    {
        dim3 grid(DIMC / 128, MROWS / 128);  // (3, 1568)
        mma_gemm<false><<<grid, 256, GEMM_SMEM_BYTES>>>(
            ahi, alo, wt_hi + proj_off, wt_lo + proj_off, proj_b, out,
            MROWS, DIMC, DIMC);
    }
}

// round 8
// speedup vs baseline: 1.3986x; 1.3986x over previous
#include <cuda_runtime.h>
#include <cuda_bf16.h>
#include <cstdint>
#include <cstddef>

#define DIMC   384
#define HEADS  12
#define HD     32
#define NTOK   49
#define BWIN   4096
#define NWIN   256
#define MROWS  (BWIN * NTOK)
#define QKVN   (3 * DIMC)
#define QSCALE 0.17677669529663687f

__device__ __nv_bfloat16 g_qh[(size_t)MROWS * QKVN];   // qkv hi (q pre-scaled)
__device__ __nv_bfloat16 g_ql[(size_t)MROWS * QKVN];   // qkv lo
__device__ __nv_bfloat16 g_xhi[(size_t)MROWS * DIMC];
__device__ __nv_bfloat16 g_xlo[(size_t)MROWS * DIMC];
__device__ __nv_bfloat16 g_ahi[(size_t)MROWS * DIMC];
__device__ __nv_bfloat16 g_alo[(size_t)MROWS * DIMC];
__device__ __nv_bfloat16 g_wt_hi[(size_t)(QKVN + DIMC) * DIMC];
__device__ __nv_bfloat16 g_wt_lo[(size_t)(QKVN + DIMC) * DIMC];
__device__ float g_comb[(size_t)NWIN * HEADS * NTOK * 64 + 4096];

__device__ __forceinline__ uint32_t smem_u32(const void* p) {
    uint32_t a;
    asm("{ .reg .u64 t; cvta.to.shared.u64 t, %1; cvt.u32.u64 %0, t; }"
        : "=r"(a) : "l"(p));
    return a;
}
__device__ __forceinline__ uint32_t sw128(uint32_t off) {
    return off ^ ((off >> 3) & 0x70);
}
__device__ __forceinline__ void ldsm4(uint32_t (&r)[4], uint32_t addr) {
    asm volatile("ldmatrix.sync.aligned.m8n8.x4.shared.b16 {%0,%1,%2,%3}, [%4];"
        : "=r"(r[0]), "=r"(r[1]), "=r"(r[2]), "=r"(r[3]) : "r"(addr));
}
__device__ __forceinline__ void ldsm4t(uint32_t (&r)[4], uint32_t addr) {
    asm volatile("ldmatrix.sync.aligned.m8n8.x4.trans.shared.b16 {%0,%1,%2,%3}, [%4];"
        : "=r"(r[0]), "=r"(r[1]), "=r"(r[2]), "=r"(r[3]) : "r"(addr));
}
__device__ __forceinline__ void mma16816(float (&d)[4], const uint32_t (&a)[4],
                                         uint32_t b0, uint32_t b1) {
    asm volatile(
        "mma.sync.aligned.m16n8k16.row.col.f32.bf16.bf16.f32 "
        "{%0,%1,%2,%3}, {%4,%5,%6,%7}, {%8,%9}, {%0,%1,%2,%3};"
        : "+f"(d[0]), "+f"(d[1]), "+f"(d[2]), "+f"(d[3])
        : "r"(a[0]), "r"(a[1]), "r"(a[2]), "r"(a[3]), "r"(b0), "r"(b1));
}
__device__ __forceinline__ void cp16(uint32_t dst, const void* src) {
    asm volatile("cp.async.cg.shared.global [%0], [%1], 16;"
                 :: "r"(dst), "l"(src));
}
#define CP_COMMIT() asm volatile("cp.async.commit_group;" ::: "memory")
#define CP_WAIT1()  asm volatile("cp.async.wait_group 1;" ::: "memory")
#define CP_WAIT0()  asm volatile("cp.async.wait_group 0;" ::: "memory")

__device__ __forceinline__ void split2(float x, float y, uint32_t& h, uint32_t& l) {
    __nv_bfloat162 hp = __floats2bfloat162_rn(x, y);
    __nv_bfloat162 lp = __floats2bfloat162_rn(x - __low2float(hp),
                                              y - __high2float(hp));
    h = *(uint32_t*)&hp;
    l = *(uint32_t*)&lp;
}

// ------------------------------- prep kernels -------------------------------
__global__ void prep_w_kernel(const float* __restrict__ W,
                              __nv_bfloat16* __restrict__ hi,
                              __nv_bfloat16* __restrict__ lo, int K, int N) {
    int idx = blockIdx.x * blockDim.x + threadIdx.x;
    if (idx >= N * K) return;
    int n = idx / K, k = idx % K;
    float x = W[(size_t)k * N + n];
    __nv_bfloat16 h = __float2bfloat16(x);
    hi[idx] = h;
    lo[idx] = __float2bfloat16(x - __bfloat162float(h));
}

__global__ void prep_x_kernel(const float* __restrict__ x,
                              __nv_bfloat16* __restrict__ hi,
                              __nv_bfloat16* __restrict__ lo, size_t n4) {
    size_t i = (size_t)blockIdx.x * blockDim.x + threadIdx.x;
    if (i >= n4) return;
    float4 xv = ((const float4*)x)[i];
    uint32_t h0, l0, h1, l1;
    split2(xv.x, xv.y, h0, l0);
    split2(xv.z, xv.w, h1, l1);
    ((uint2*)hi)[i] = make_uint2(h0, h1);
    ((uint2*)lo)[i] = make_uint2(l0, l1);
}

// comb[w][h][R][C64] = mask[w][R][C] + clip(bias,+-5); 0 for C>=49
__global__ void prep_comb_kernel(const float* __restrict__ mask,
                                 const float* __restrict__ table,
                                 const int* __restrict__ idx,
                                 float* __restrict__ out) {
    int e = blockIdx.x * blockDim.x + threadIdx.x;
    if (e >= NWIN * HEADS * NTOK * 64) return;
    int C = e & 63, R = (e >> 6) % NTOK;
    int wh = e / (NTOK * 64);
    int w = wh / HEADS, h = wh % HEADS;
    float v = 0.f;
    if (C < NTOK) {
        float b = table[idx[R * NTOK + C] * HEADS + h];
        v = mask[(size_t)w * NTOK * NTOK + R * NTOK + C]
          + fminf(fmaxf(b, -5.f), 5.f);
    }
    out[e] = v;
}

// ---------------- HMMA bf16-split GEMM (R5 config, BK=64, 3 stages) ---------
#define GEMM_SMEM_BYTES (3 * 65536)

template <bool QKV, bool SPLIT>
__global__ __launch_bounds__(256, 1) void mma_gemm(
    const __nv_bfloat16* __restrict__ Ahi, const __nv_bfloat16* __restrict__ Alo,
    const __nv_bfloat16* __restrict__ Bhi, const __nv_bfloat16* __restrict__ Blo,
    const float* __restrict__ bias, float* __restrict__ C,
    __nv_bfloat16* __restrict__ Chi, __nv_bfloat16* __restrict__ Clo,
    int M, int N, int K)
{
    extern __shared__ char smem[];
    const uint32_t sb = smem_u32(smem);
    const int tid = threadIdx.x, lane = tid & 31, wid = tid >> 5;
    const int wm = wid & 3, wn = wid >> 2;
    const int bm = blockIdx.y * 128, bn = blockIdx.x * 128;
    const int NCH = K / 64;
    const int crow = tid >> 3, cpos = tid & 7;

    auto cp_stage = [&](int s, int ch) {
        const int k0 = ch * 64;
        const uint32_t st = sb + s * 65536;
        #pragma unroll
        for (int t = 0; t < 4; t++) {
            const int row = t * 32 + crow;
            const uint32_t soff = sw128((uint32_t)(row * 128 + cpos * 16));
            const size_t ga = (size_t)(bm + row) * K + k0 + cpos * 8;
            const size_t gb = (size_t)(bn + row) * K + k0 + cpos * 8;
            cp16(st + soff,         Ahi + ga);
            cp16(st + 16384 + soff, Alo + ga);
            cp16(st + 32768 + soff, Bhi + gb);
            cp16(st + 49152 + soff, Blo + gb);
        }
    };

    float acc[2][8][4] = {};

    auto domma = [&](int s) {
        const uint32_t sA = sb + s * 65536, sB = sA + 32768;
        #pragma unroll
        for (int ks = 0; ks < 4; ks++) {
            const int cb = ks * 32 + (lane >> 4) * 16;
            uint32_t ah[2][4], al[2][4];
            #pragma unroll
            for (int mt = 0; mt < 2; mt++) {
                const int r = wm * 32 + mt * 16 + (lane & 15);
                const uint32_t o = sw128((uint32_t)(r * 128 + cb));
                ldsm4(ah[mt], sA + o);
                ldsm4(al[mt], sA + 16384 + o);
            }
            uint32_t bh[4][4], bl[4][4];
            #pragma unroll
            for (int g = 0; g < 4; g++) {
                const int r = wn * 64 + g * 16 + (lane & 15);
                const uint32_t o = sw128((uint32_t)(r * 128 + cb));
                ldsm4(bh[g], sB + o);
                ldsm4(bl[g], sB + 16384 + o);
            }
            #pragma unroll
            for (int mt = 0; mt < 2; mt++)
                #pragma unroll
                for (int nt = 0; nt < 8; nt++) {
                    const int g = nt >> 1, o = nt & 1;
                    mma16816(acc[mt][nt], ah[mt], bh[g][o], bh[g][o + 2]);
                    mma16816(acc[mt][nt], al[mt], bh[g][o], bh[g][o + 2]);
                    mma16816(acc[mt][nt], ah[mt], bl[g][o], bl[g][o + 2]);
                }
        }
    };

    cp_stage(0, 0); CP_COMMIT();
    cp_stage(1, 1); CP_COMMIT();
    for (int ch = 0; ch < NCH; ch++) {
        const int s = ch % 3;
        CP_WAIT1();
        __syncthreads();
        if (ch + 2 < NCH) cp_stage((ch + 2) % 3, ch + 2);
        CP_COMMIT();
        domma(s);
    }

    const float qs = (QKV && bn < DIMC) ? QSCALE : 1.0f;
    #pragma unroll
    for (int mt = 0; mt < 2; mt++) {
        const int r0 = bm + wm * 32 + mt * 16 + (lane >> 2);
        #pragma unroll
        for (int nt = 0; nt < 8; nt++) {
            const int c0 = bn + wn * 64 + nt * 8 + (lane & 3) * 2;
            const float2 bv = *(const float2*)(bias + c0);
            float x0 = (acc[mt][nt][0] + bv.x) * qs;
            float y0 = (acc[mt][nt][1] + bv.y) * qs;
            float x1 = (acc[mt][nt][2] + bv.x) * qs;
            float y1 = (acc[mt][nt][3] + bv.y) * qs;
            if (SPLIT) {
                uint32_t hp, lp;
                split2(x0, y0, hp, lp);
                *(uint32_t*)(Chi + (size_t)r0 * N + c0) = hp;
                *(uint32_t*)(Clo + (size_t)r0 * N + c0) = lp;
                split2(x1, y1, hp, lp);
                *(uint32_t*)(Chi + (size_t)(r0 + 8) * N + c0) = hp;
                *(uint32_t*)(Clo + (size_t)(r0 + 8) * N + c0) = lp;
            } else {
                *(float2*)(C + (size_t)r0 * N + c0)       = make_float2(x0, y0);
                *(float2*)(C + (size_t)(r0 + 8) * N + c0) = make_float2(x1, y1);
            }
        }
    }
}

// ---------------- Attention v3: HMMA + register softmax --------------------
// CTA = 128 thr = 4 warps = heads hg*4.. of one window (3 CTAs/window).
// smem: 6 blocks (Qh Ql Kh Kl Vh Vl) x 16KB; block = 2 sub-tiles of 8KB,
// sub-tile = 64 rows x 128B ([head 2t | head 2t+1] 64B each), SW128.
#define ATTN_SMEM_BYTES (6 * 16384)

__global__ __launch_bounds__(128, 2) void attn_mma_kernel(
    const __nv_bfloat16* __restrict__ qh_g, const __nv_bfloat16* __restrict__ ql_g,
    const float* __restrict__ comb,
    __nv_bfloat16* __restrict__ ohi, __nv_bfloat16* __restrict__ olo)
{
    extern __shared__ char smem[];
    const uint32_t sb = smem_u32(smem);
    const int tid = threadIdx.x, lane = tid & 31, wid = tid >> 5;
    const int b = blockIdx.x / 3, hg = blockIdx.x % 3;
    const int h = hg * 4 + wid;

    // zero pad rows 49..63 of all 12 sub-tiles
    for (int i = tid; i < 12 * 15 * 8; i += 128) {
        const int t = i / 120, rr = 49 + (i % 120) / 8, q4 = i % 8;
        *(uint4*)(smem + t * 8192 + sw128((uint32_t)(rr * 128 + q4 * 16))) =
            make_uint4(0, 0, 0, 0);
    }
    // stage q/k/v hi/lo: 49 rows x 6 matrix-halves x 16 chunks of 16B
    {
        const size_t rowbase = (size_t)b * NTOK * QKVN;
        for (int i = tid; i < NTOK * 96; i += 128) {
            const int n = i / 96, rem = i % 96;
            const int mh = rem >> 4, ck = rem & 15;
            const int mat = mh >> 1, half = mh & 1;
            const __nv_bfloat16* src = (half ? ql_g : qh_g)
                + rowbase + (size_t)n * QKVN + mat * DIMC + hg * 128 + ck * 8;
            const uint32_t dst = sb + mh * 16384 + (ck >> 3) * 8192
                               + sw128((uint32_t)(n * 128 + (ck & 7) * 16));
            cp16(dst, src);
        }
    }
    CP_COMMIT(); CP_WAIT0();
    __syncthreads();

    const int t = wid >> 1, th = wid & 1;
    const uint32_t Qh = sb + t * 8192;
    const uint32_t Ql = Qh + 16384, Kh = Qh + 32768, Kl = Qh + 49152;
    const uint32_t Vh = Qh + 65536, Vl = Qh + 81920;

    // S = Q @ K^T (64x56, k=32)
    float acc[4][7][4] = {};
    #pragma unroll
    for (int ks = 0; ks < 2; ks++) {
        const uint32_t qb = (uint32_t)(th * 64 + (2 * ks + (lane >> 4)) * 16);
        uint32_t qfh[4][4], qfl[4][4];
        #pragma unroll
        for (int mt = 0; mt < 4; mt++) {
            const int r = mt * 16 + (lane & 15);
            ldsm4(qfh[mt], Qh + sw128((uint32_t)(r * 128) + qb));
            ldsm4(qfl[mt], Ql + sw128((uint32_t)(r * 128) + qb));
        }
        #pragma unroll
        for (int g = 0; g < 4; g++) {
            const int rk = g * 16 + (lane & 15);
            uint32_t kfh[4], kfl[4];
            ldsm4(kfh, Kh + sw128((uint32_t)(rk * 128) + qb));
            ldsm4(kfl, Kl + sw128((uint32_t)(rk * 128) + qb));
            #pragma unroll
            for (int o = 0; o < 2; o++) {
                const int nt = g * 2 + o;
                if (nt == 7) continue;
                #pragma unroll
                for (int mt = 0; mt < 4; mt++) {
                    mma16816(acc[mt][nt], qfh[mt], kfh[o], kfh[o + 2]);
                    mma16816(acc[mt][nt], qfl[mt], kfh[o], kfh[o + 2]);
                    mma16816(acc[mt][nt], qfh[mt], kfl[o], kfl[o + 2]);
                }
            }
        }
    }

    // + comb, clip +-10, mask padded cols
    const float* cw = comb + ((size_t)(b & (NWIN - 1)) * HEADS + h) * (NTOK * 64);
    #pragma unroll
    for (int mt = 0; mt < 4; mt++)
        #pragma unroll
        for (int nt = 0; nt < 7; nt++) {
            const int C0 = nt * 8 + 2 * (lane & 3);
            #pragma unroll
            for (int rh = 0; rh < 2; rh++) {
                const int R = mt * 16 + (lane >> 2) + rh * 8;
                const float2 cb = *(const float2*)(cw + R * 64 + C0);
                float s0 = fminf(fmaxf(acc[mt][nt][rh*2]   + cb.x, -10.f), 10.f);
                float s1 = fminf(fmaxf(acc[mt][nt][rh*2+1] + cb.y, -10.f), 10.f);
                if (nt == 6) {
                    if (C0 >= NTOK)     s0 = -1e30f;
                    if (C0 + 1 >= NTOK) s1 = -1e30f;
                }
                acc[mt][nt][rh*2]   = s0;
                acc[mt][nt][rh*2+1] = s1;
            }
        }

    // register softmax (row on 4 lanes)
    #pragma unroll
    for (int mt = 0; mt < 4; mt++)
        #pragma unroll
        for (int rh = 0; rh < 2; rh++) {
            float mx = -1e30f;
            #pragma unroll
            for (int nt = 0; nt < 7; nt++)
                mx = fmaxf(mx, fmaxf(acc[mt][nt][rh*2], acc[mt][nt][rh*2+1]));
            mx = fmaxf(mx, __shfl_xor_sync(0xffffffffu, mx, 1));
            mx = fmaxf(mx, __shfl_xor_sync(0xffffffffu, mx, 2));
            float sum = 0.f;
            #pragma unroll
            for (int nt = 0; nt < 7; nt++) {
                float e0 = __expf(acc[mt][nt][rh*2]   - mx);
                float e1 = __expf(acc[mt][nt][rh*2+1] - mx);
                acc[mt][nt][rh*2] = e0; acc[mt][nt][rh*2+1] = e1;
                sum += e0 + e1;
            }
            sum += __shfl_xor_sync(0xffffffffu, sum, 1);
            sum += __shfl_xor_sync(0xffffffffu, sum, 2);
            const float inv = 1.f / sum;
            #pragma unroll
            for (int nt = 0; nt < 7; nt++) {
                acc[mt][nt][rh*2] *= inv; acc[mt][nt][rh*2+1] *= inv;
            }
        }

    // out = P @ V (k = 64 tokens, n = 32 d)
    float oacc[4][4][4] = {};
    #pragma unroll
    for (int kk = 0; kk < 4; kk++) {
        uint32_t vfh[2][4], vfl[2][4];
        #pragma unroll
        for (int dp = 0; dp < 2; dp++) {
            const int rm = kk * 16 + (lane & 15);
            const uint32_t vb = (uint32_t)(th * 64 + dp * 32 + (lane >> 4) * 16);
            ldsm4t(vfh[dp], Vh + sw128((uint32_t)(rm * 128) + vb));
            ldsm4t(vfl[dp], Vl + sw128((uint32_t)(rm * 128) + vb));
        }
        const int nta = kk * 2, ntb = kk * 2 + 1;
        #pragma unroll
        for (int mt = 0; mt < 4; mt++) {
            uint32_t ph[4], pl[4];
            split2(acc[mt][nta][0], acc[mt][nta][1], ph[0], pl[0]);
            split2(acc[mt][nta][2], acc[mt][nta][3], ph[1], pl[1]);
            if (ntb < 7) {
                split2(acc[mt][ntb][0], acc[mt][ntb][1], ph[2], pl[2]);
                split2(acc[mt][ntb][2], acc[mt][ntb][3], ph[3], pl[3]);
            } else {
                ph[2] = ph[3] = pl[2] = pl[3] = 0u;
            }
            #pragma unroll
            for (int dp = 0; dp < 2; dp++)
                #pragma unroll
                for (int o = 0; o < 2; o++) {
                    const int dt = dp * 2 + o;
                    mma16816(oacc[mt][dt], ph, vfh[dp][2*o], vfh[dp][2*o+1]);
                    mma16816(oacc[mt][dt], pl, vfh[dp][2*o], vfh[dp][2*o+1]);
                    mma16816(oacc[mt][dt], ph, vfl[dp][2*o], vfl[dp][2*o+1]);
                }
        }
    }

    // store bf16 hi/lo
    const size_t ob = (size_t)b * NTOK * DIMC + h * HD;
    #pragma unroll
    for (int mt = 0; mt < 4; mt++)
        #pragma unroll
        for (int rh = 0; rh < 2; rh++) {
            const int R = mt * 16 + (lane >> 2) + rh * 8;
            if (R < NTOK) {
                #pragma unroll
                for (int dt = 0; dt < 4; dt++) {
                    uint32_t hp, lp;
                    split2(oacc[mt][dt][rh*2], oacc[mt][dt][rh*2+1], hp, lp);
                    const size_t o = ob + (size_t)R * DIMC + dt * 8 + 2 * (lane & 3);
                    *(uint32_t*)(ohi + o) = hp;
                    *(uint32_t*)(olo + o) = lp;
                }
            }
        }
}

// ---------------------------------------------------------------------------
extern "C" void kernel_launch(void* const* d_in, const int* in_sizes, int n_in,
                              void* d_out, int out_size)
{
    const float* x         = (const float*)d_in[0];
    const float* mask      = (const float*)d_in[1];
    const float* qkv_w     = (const float*)d_in[2];
    const float* qkv_b     = (const float*)d_in[3];
    const float* proj_w    = (const float*)d_in[4];
    const float* proj_b    = (const float*)d_in[5];
    const float* rel_table = (const float*)d_in[6];
    const int*   rel_index = (const int*)d_in[7];
    float*       out       = (float*)d_out;

    float* combbuf = nullptr;
    __nv_bfloat16 *qh, *ql, *xhi, *xlo, *ahi, *alo, *wt_hi, *wt_lo;
    cudaGetSymbolAddress((void**)&combbuf, g_comb);
    cudaGetSymbolAddress((void**)&qh, g_qh);
    cudaGetSymbolAddress((void**)&ql, g_ql);
    cudaGetSymbolAddress((void**)&xhi, g_xhi);
    cudaGetSymbolAddress((void**)&xlo, g_xlo);
    cudaGetSymbolAddress((void**)&ahi, g_ahi);
    cudaGetSymbolAddress((void**)&alo, g_alo);
    cudaGetSymbolAddress((void**)&wt_hi, g_wt_hi);
    cudaGetSymbolAddress((void**)&wt_lo, g_wt_lo);

    static int _once = []() {
        cudaFuncSetAttribute(mma_gemm<true, true>,
            cudaFuncAttributeMaxDynamicSharedMemorySize, GEMM_SMEM_BYTES);
        cudaFuncSetAttribute(mma_gemm<false, false>,
            cudaFuncAttributeMaxDynamicSharedMemorySize, GEMM_SMEM_BYTES);
        cudaFuncSetAttribute(attn_mma_kernel,
            cudaFuncAttributeMaxDynamicSharedMemorySize, ATTN_SMEM_BYTES);
        return 0;
    }();
    (void)_once;

    const size_t proj_off = (size_t)QKVN * DIMC;

    prep_w_kernel<<<(QKVN * DIMC + 255) / 256, 256>>>(qkv_w, wt_hi, wt_lo,
                                                      DIMC, QKVN);
    prep_w_kernel<<<(DIMC * DIMC + 255) / 256, 256>>>(
        proj_w, wt_hi + proj_off, wt_lo + proj_off, DIMC, DIMC);
    prep_comb_kernel<<<(NWIN * HEADS * NTOK * 64 + 255) / 256, 256>>>(
        mask, rel_table, rel_index, combbuf);
    {
        const size_t n4 = (size_t)MROWS * DIMC / 4;
        prep_x_kernel<<<(unsigned)((n4 + 255) / 256), 256>>>(x, xhi, xlo, n4);
    }

    {   // QKV GEMM -> bf16 hi/lo
        dim3 grid(QKVN / 128, MROWS / 128);
        mma_gemm<true, true><<<grid, 256, GEMM_SMEM_BYTES>>>(
            xhi, xlo, wt_hi, wt_lo, qkv_b, nullptr, qh, ql, MROWS, QKVN, DIMC);
    }

    attn_mma_kernel<<<BWIN * 3, 128, ATTN_SMEM_BYTES>>>(qh, ql, combbuf,
                                                        ahi, alo);

    {   // proj GEMM -> fp32 out
        dim3 grid(DIMC / 128, MROWS / 128);
        mma_gemm<false, false><<<grid, 256, GEMM_SMEM_BYTES>>>(
            ahi, alo, wt_hi + proj_off, wt_lo + proj_off, proj_b, out,
            nullptr, nullptr, MROWS, DIMC, DIMC);
    }
}